// round 13
// baseline (speedup 1.0000x reference)
#include <cuda_runtime.h>
#include <cuda_fp16.h>

// Problem constants (fixed shapes from reference)
#define VV 100000
#define DD 64
#define BB 4096
#define LL 50
#define KK 3
#define NBAGS (BB * (2 + KK))   // 20480
#define MAX_NORM 20.0f

#define CTAS 1184                // 148 SMs * 8 resident CTAs -> all co-resident
#define ROWS_PER_PASS (CTAS * 256 / 8)   // 37888 rows renormed per grid pass

// Renormed embedding table in fp16 (12.8 MB).
__device__ __half d_table[VV * DD];

// Grid barrier state. bar_gen increases monotonically across launches/replays
// (sense reversal); bar_count is reset to 0 by the last arriver each launch,
// so behavior is identical on every call (deterministic).
__device__ unsigned bar_count = 0;
__device__ unsigned bar_gen   = 0;

// Fused kernel: phase 1 renorm (grid-strided), grid spin-barrier, phase 2
// embedding-bag sum (persistent, R7/R12 verified-optimal body).
// __launch_bounds__(256, 8) forces regs <= 32 so all 1184 CTAs are resident
// (2048 thr/SM, smem 0) -> the spin barrier cannot deadlock.
__global__ __launch_bounds__(256, 8) void fused_kernel(
    const float* __restrict__ emb,
    const int* __restrict__ tl,
    const int* __restrict__ tr,
    const int* __restrict__ tn,
    float* __restrict__ out)
{
    int tid = threadIdx.x;

    // ---------- Phase 1: renorm rows into fp16 table ----------
    {
        int lane8 = tid & 7;
        int base  = (blockIdx.x * 256 + tid) >> 3;
        const float4* e4 = (const float4*)emb;

        for (int row = base; row < VV; row += ROWS_PER_PASS) {
            float4 v0 = e4[row * 16 + lane8 * 2 + 0];
            float4 v1 = e4[row * 16 + lane8 * 2 + 1];

            float ss = v0.x*v0.x + v0.y*v0.y + v0.z*v0.z + v0.w*v0.w
                     + v1.x*v1.x + v1.y*v1.y + v1.z*v1.z + v1.w*v1.w;
            ss += __shfl_xor_sync(0xffffffffu, ss, 1);
            ss += __shfl_xor_sync(0xffffffffu, ss, 2);
            ss += __shfl_xor_sync(0xffffffffu, ss, 4);

            float norm = sqrtf(ss);
            float s = (norm > MAX_NORM) ? (MAX_NORM / norm) : 1.0f;

            __half2 h0 = __floats2half2_rn(v0.x * s, v0.y * s);
            __half2 h1 = __floats2half2_rn(v0.z * s, v0.w * s);
            __half2 h2 = __floats2half2_rn(v1.x * s, v1.y * s);
            __half2 h3 = __floats2half2_rn(v1.z * s, v1.w * s);
            uint4 packed;
            packed.x = *reinterpret_cast<unsigned*>(&h0);
            packed.y = *reinterpret_cast<unsigned*>(&h1);
            packed.z = *reinterpret_cast<unsigned*>(&h2);
            packed.w = *reinterpret_cast<unsigned*>(&h3);
            ((uint4*)d_table)[row * 8 + lane8] = packed;
        }
    }

    // ---------- Grid barrier (sense reversal, all CTAs resident) ----------
    __syncthreads();
    if (tid == 0) {
        __threadfence();                        // table writes visible GPU-wide
        unsigned gen = *((volatile unsigned*)&bar_gen);
        unsigned v = atomicAdd(&bar_count, 1);
        if (v == CTAS - 1) {
            bar_count = 0;                      // reset for next launch
            __threadfence();
            atomicAdd(&bar_gen, 1);             // release everyone
        } else {
            while (*((volatile unsigned*)&bar_gen) == gen) { }
        }
        __threadfence();                        // acquire
    }
    __syncthreads();

    // ---------- Phase 2: embedding-bag sum (R7/R12 body) ----------
    {
        int warp  = tid >> 5;
        int lane  = tid & 31;
        int sub   = lane >> 3;     // token slot 0..3 within an iteration
        int dlane = lane & 7;      // which 16 B of the 128 B row

        const uint4* t4 = (const uint4*)d_table;   // 8 uint4 per row
        const int nwarps = CTAS * 8;

        for (int bag = blockIdx.x * 8 + warp; bag < NBAGS; bag += nwarps) {
            const int* p;
            if (bag < BB)          p = tl + bag * LL;
            else if (bag < 2 * BB) p = tr + (bag - BB) * LL;
            else                   p = tn + (bag - 2 * BB) * LL;

            float acc[8] = {0.f, 0.f, 0.f, 0.f, 0.f, 0.f, 0.f, 0.f};

            // 12 full iterations of 4 tokens
            #pragma unroll
            for (int t = 0; t < 48; t += 4) {
                int tok = p[t + sub];                  // uniform in 8-lane group
                uint4 v = __ldg(&t4[tok * 8 + dlane]);
                float2 fa = __half22float2(*reinterpret_cast<__half2*>(&v.x));
                float2 fb = __half22float2(*reinterpret_cast<__half2*>(&v.y));
                float2 fc = __half22float2(*reinterpret_cast<__half2*>(&v.z));
                float2 fd = __half22float2(*reinterpret_cast<__half2*>(&v.w));
                acc[0] += fa.x; acc[1] += fa.y;
                acc[2] += fb.x; acc[3] += fb.y;
                acc[4] += fc.x; acc[5] += fc.y;
                acc[6] += fd.x; acc[7] += fd.y;
            }
            // tail: tokens 48,49 handled by sub 0,1 only
            if (sub < 2) {
                int tok = p[48 + sub];
                uint4 v = __ldg(&t4[tok * 8 + dlane]);
                float2 fa = __half22float2(*reinterpret_cast<__half2*>(&v.x));
                float2 fb = __half22float2(*reinterpret_cast<__half2*>(&v.y));
                float2 fc = __half22float2(*reinterpret_cast<__half2*>(&v.z));
                float2 fd = __half22float2(*reinterpret_cast<__half2*>(&v.w));
                acc[0] += fa.x; acc[1] += fa.y;
                acc[2] += fb.x; acc[3] += fb.y;
                acc[4] += fc.x; acc[5] += fc.y;
                acc[6] += fd.x; acc[7] += fd.y;
            }

            // Combine the 4 sub-group partials (lane bits 3,4 index sub).
            #pragma unroll
            for (int i = 0; i < 8; ++i) {
                acc[i] += __shfl_xor_sync(0xffffffffu, acc[i], 8);
                acc[i] += __shfl_xor_sync(0xffffffffu, acc[i], 16);
            }

            // Each lane writes 2 dims -> 256 B/warp contiguous.
            float2 w = make_float2(acc[sub * 2], acc[sub * 2 + 1]);
            ((float2*)out)[bag * 32 + dlane * 4 + sub] = w;
        }
    }
}

extern "C" void kernel_launch(void* const* d_in, const int* in_sizes, int n_in,
                              void* d_out, int out_size) {
    const float* emb = (const float*)d_in[0];
    const int*   tl  = (const int*)d_in[1];
    const int*   tr  = (const int*)d_in[2];
    const int*   tn  = (const int*)d_in[3];
    float*       out = (float*)d_out;

    fused_kernel<<<CTAS, 256>>>(emb, tl, tr, tn, out);
}

// round 16
// speedup vs baseline: 1.0880x; 1.0880x over previous
#include <cuda_runtime.h>
#include <cuda_fp16.h>

// Problem constants (fixed shapes from reference)
#define VV 100000
#define DD 64
#define BB 4096
#define LL 50
#define KK 3
#define NBAGS (BB * (2 + KK))   // 20480
#define MAX_NORM 20.0f

#define BAG_CTAS 1184            // 148 SMs * 8 resident CTAs -> exactly one wave

// Renormed embedding table in fp16 (12.8 MB).
__device__ __half d_table[VV * DD];

// Kernel 1: renorm rows. 8 lanes per row; each lane reads 8 floats (2x float4),
// reduces norm across 8 lanes, writes 8 halves (uint4, 16 B).
__global__ __launch_bounds__(256) void renorm_kernel(const float* __restrict__ emb) {
    int idx  = blockIdx.x * blockDim.x + threadIdx.x;
    int row  = idx >> 3;
    int lane = threadIdx.x & 7;
    if (row >= VV) return;

    const float4* e4 = (const float4*)emb;
    float4 v0 = e4[row * 16 + lane * 2 + 0];
    float4 v1 = e4[row * 16 + lane * 2 + 1];

    float ss = v0.x*v0.x + v0.y*v0.y + v0.z*v0.z + v0.w*v0.w
             + v1.x*v1.x + v1.y*v1.y + v1.z*v1.z + v1.w*v1.w;
    ss += __shfl_xor_sync(0xffffffffu, ss, 1);
    ss += __shfl_xor_sync(0xffffffffu, ss, 2);
    ss += __shfl_xor_sync(0xffffffffu, ss, 4);

    float norm = sqrtf(ss);
    float s = (norm > MAX_NORM) ? (MAX_NORM / norm) : 1.0f;

    __half2 h0 = __floats2half2_rn(v0.x * s, v0.y * s);
    __half2 h1 = __floats2half2_rn(v0.z * s, v0.w * s);
    __half2 h2 = __floats2half2_rn(v1.x * s, v1.y * s);
    __half2 h3 = __floats2half2_rn(v1.z * s, v1.w * s);
    uint4 packed;
    packed.x = *reinterpret_cast<unsigned*>(&h0);
    packed.y = *reinterpret_cast<unsigned*>(&h1);
    packed.z = *reinterpret_cast<unsigned*>(&h2);
    packed.w = *reinterpret_cast<unsigned*>(&h3);
    ((uint4*)d_table)[row * 8 + lane] = packed;
}

// Kernel 2: embedding-bag sum. PERSISTENT grid (one wave, 1184 CTAs) with a
// grid-stride loop over bags; each warp processes 2-3 bags sequentially.
// Inner body is the verified-optimal R7 shape: the warp's four 8-lane groups
// each gather a DIFFERENT token per iteration (uint4 = 16 B/lane -> 4 x 128 B
// lines per warp-LDG), 13 gather-LDGs/bag, 2-round shfl-xor reduction.
// Bag order matches output tuple flatten: [l (B) | r (B) | neg (B*K)].
__global__ __launch_bounds__(256) void bag_kernel(
    const int* __restrict__ tl,
    const int* __restrict__ tr,
    const int* __restrict__ tn,
    float* __restrict__ out)
{
    int warp  = threadIdx.x >> 5;
    int lane  = threadIdx.x & 31;
    int sub   = lane >> 3;     // token slot 0..3 within an iteration
    int dlane = lane & 7;      // which 16 B of the 128 B row

    const uint4* t4 = (const uint4*)d_table;   // 8 uint4 per row
    const int nwarps = BAG_CTAS * 8;

    for (int bag = blockIdx.x * 8 + warp; bag < NBAGS; bag += nwarps) {
        const int* p;
        if (bag < BB)          p = tl + bag * LL;
        else if (bag < 2 * BB) p = tr + (bag - BB) * LL;
        else                   p = tn + (bag - 2 * BB) * LL;

        float acc[8] = {0.f, 0.f, 0.f, 0.f, 0.f, 0.f, 0.f, 0.f};

        // 12 full iterations of 4 tokens
        #pragma unroll
        for (int t = 0; t < 48; t += 4) {
            int tok = p[t + sub];                  // uniform across 8-lane group
            uint4 v = __ldg(&t4[tok * 8 + dlane]);
            __half2 a = *reinterpret_cast<__half2*>(&v.x);
            __half2 b = *reinterpret_cast<__half2*>(&v.y);
            __half2 c = *reinterpret_cast<__half2*>(&v.z);
            __half2 d = *reinterpret_cast<__half2*>(&v.w);
            float2 fa = __half22float2(a);
            float2 fb = __half22float2(b);
            float2 fc = __half22float2(c);
            float2 fd = __half22float2(d);
            acc[0] += fa.x; acc[1] += fa.y;
            acc[2] += fb.x; acc[3] += fb.y;
            acc[4] += fc.x; acc[5] += fc.y;
            acc[6] += fd.x; acc[7] += fd.y;
        }
        // tail: tokens 48,49 handled by sub 0,1 only
        if (sub < 2) {
            int tok = p[48 + sub];
            uint4 v = __ldg(&t4[tok * 8 + dlane]);
            __half2 a = *reinterpret_cast<__half2*>(&v.x);
            __half2 b = *reinterpret_cast<__half2*>(&v.y);
            __half2 c = *reinterpret_cast<__half2*>(&v.z);
            __half2 d = *reinterpret_cast<__half2*>(&v.w);
            float2 fa = __half22float2(a);
            float2 fb = __half22float2(b);
            float2 fc = __half22float2(c);
            float2 fd = __half22float2(d);
            acc[0] += fa.x; acc[1] += fa.y;
            acc[2] += fb.x; acc[3] += fb.y;
            acc[4] += fc.x; acc[5] += fc.y;
            acc[6] += fd.x; acc[7] += fd.y;
        }

        // Combine the 4 sub-group partials (lane bits 3,4 index sub).
        #pragma unroll
        for (int i = 0; i < 8; ++i) {
            acc[i] += __shfl_xor_sync(0xffffffffu, acc[i], 8);
            acc[i] += __shfl_xor_sync(0xffffffffu, acc[i], 16);
        }

        // acc[i] on this lane = dim dlane*8 + i (replicated across sub).
        // Each lane writes 2 dims -> 256 B/warp contiguous.
        float2 w = make_float2(acc[sub * 2], acc[sub * 2 + 1]);
        ((float2*)out)[bag * 32 + dlane * 4 + sub] = w;
    }
}

extern "C" void kernel_launch(void* const* d_in, const int* in_sizes, int n_in,
                              void* d_out, int out_size) {
    const float* emb = (const float*)d_in[0];
    const int*   tl  = (const int*)d_in[1];
    const int*   tr  = (const int*)d_in[2];
    const int*   tn  = (const int*)d_in[3];
    float*       out = (float*)d_out;

    int renorm_blocks = (VV * 8 + 255) / 256;    // 3125 (32 rows per block)
    renorm_kernel<<<renorm_blocks, 256>>>(emb);

    bag_kernel<<<BAG_CTAS, 256>>>(tl, tr, tn, out);
}